// round 2
// baseline (speedup 1.0000x reference)
#include <cuda_runtime.h>
#include <cuda_bf16.h>
#include <math.h>

#define F_IN    4096
#define NBLK    2048
#define NROUNDS 12
#define M_ROWS  8192
#define N_ROWS  4096

#define ROT_R 4
#define ROT_T 512

// ---------------- scratch (static device arrays; no allocation) ----------------
__device__ float       g_scratch[(size_t)M_ROWS * F_IN];   // 128 MB, reused for x then w
__device__ signed char g_qx[(size_t)M_ROWS * F_IN];        // 32 MB
__device__ signed char g_qw[(size_t)N_ROWS * F_IN];        // 16 MB
__device__ int         g_sx[M_ROWS];
__device__ int         g_sw[N_ROWS];
__device__ unsigned    g_mm[4];                            // minx,maxx,minw,maxw (ordered-uint)

// order-preserving float<->uint maps for atomic min/max on floats
__device__ __forceinline__ unsigned f2u_ord(float f) {
    unsigned u = __float_as_uint(f);
    return (u & 0x80000000u) ? ~u : (u | 0x80000000u);
}
__device__ __forceinline__ float u2f_ord(unsigned u) {
    return __uint_as_float((u & 0x80000000u) ? (u ^ 0x80000000u) : ~u);
}

__global__ void init_kernel() {
    g_mm[0] = 0xFFFFFFFFu; g_mm[1] = 0u;   // x: min-acc, max-acc
    g_mm[2] = 0xFFFFFFFFu; g_mm[3] = 0u;   // w
}

// ---------------- rotation: 12 rounds fully in shared memory, 4 rows/CTA ----------------
// sel: 0 -> accumulate min/max into g_mm[0..1] (x), 2 -> g_mm[2..3] (w)
__global__ __launch_bounds__(ROT_T) void rotate_kernel(
    const float* __restrict__ src,
    const int* __restrict__ perm, const float* __restrict__ mats, int sel)
{
    extern __shared__ float sm[];
    float* buf0 = sm;
    float* buf1 = sm + ROT_R * F_IN;
    const int tid = threadIdx.x;
    const size_t base = (size_t)blockIdx.x * ROT_R * F_IN;

    // load 4 rows, coalesced float4
    {
        const float4* g = (const float4*)(src + base);
        float4* b = (float4*)buf0;
        #pragma unroll
        for (int i = 0; i < (ROT_R * F_IN / 4) / ROT_T; i++)
            b[tid + i * ROT_T] = g[tid + i * ROT_T];
    }
    __syncthreads();

    float* cur = buf0;
    float* nxt = buf1;
    float mn = 3.0e38f, mx = -3.0e38f;

    for (int r = 0; r < NROUNDS; r++) {
        const int2*   pr = (const int2*)(perm + r * F_IN);
        const float4* mr = (const float4*)(mats + (size_t)r * NBLK * 4);
        const bool last = (r == NROUNDS - 1);
        #pragma unroll
        for (int b = 0; b < NBLK / ROT_T; b++) {
            const int k = tid + b * ROT_T;
            const int2   p = pr[k];   // perm[2k], perm[2k+1]  (L2-resident constants)
            const float4 m = mr[k];   // 2x2 block {m00,m01,m10,m11}
            #pragma unroll
            for (int row = 0; row < ROT_R; row++) {
                const float v0 = cur[row * F_IN + p.x];
                const float v1 = cur[row * F_IN + p.y];
                const float o0 = m.x * v0 + m.y * v1;
                const float o1 = m.z * v0 + m.w * v1;
                ((float2*)(nxt + row * F_IN))[k] = make_float2(o0, o1);
                if (last) {
                    mn = fminf(mn, fminf(o0, o1));
                    mx = fmaxf(mx, fmaxf(o0, o1));
                }
            }
        }
        __syncthreads();
        float* t = cur; cur = nxt; nxt = t;
    }

    // write rotated rows (fp32 scratch)
    {
        float4* g = (float4*)(g_scratch + base);
        const float4* b = (const float4*)cur;
        #pragma unroll
        for (int i = 0; i < (ROT_R * F_IN / 4) / ROT_T; i++)
            g[tid + i * ROT_T] = b[tid + i * ROT_T];
    }

    // block-reduce min/max -> one atomic pair per CTA
    #pragma unroll
    for (int o = 16; o > 0; o >>= 1) {
        mn = fminf(mn, __shfl_xor_sync(0xFFFFFFFFu, mn, o));
        mx = fmaxf(mx, __shfl_xor_sync(0xFFFFFFFFu, mx, o));
    }
    __shared__ float smn[ROT_T / 32], smx[ROT_T / 32];
    const int w = tid >> 5;
    if ((tid & 31) == 0) { smn[w] = mn; smx[w] = mx; }
    __syncthreads();
    if (tid == 0) {
        #pragma unroll
        for (int i = 1; i < ROT_T / 32; i++) {
            mn = fminf(mn, smn[i]); mx = fmaxf(mx, smx[i]);
        }
        atomicMin(&g_mm[sel], f2u_ord(mn));
        atomicMax(&g_mm[sel + 1], f2u_ord(mx));
    }
}

// ---------------- quantize: q = clip(round((t-lo)/s) - 128), + per-row sums ----------------
// qdst/rowsum selected by template-free flag: is_w ? (g_qw,g_sw) : (g_qx,g_sx)
__global__ __launch_bounds__(256) void quant_kernel(int sel)
{
    const int row = blockIdx.x;
    const int tid = threadIdx.x;
    signed char* q = sel ? g_qw : g_qx;
    int* rowsum    = sel ? g_sw : g_sx;
    const float lo = u2f_ord(g_mm[sel ? 2 : 0]);
    const float hi = u2f_ord(g_mm[sel ? 3 : 1]);
    const float scale = (hi - lo) / 255.0f;

    const float4* s4 = (const float4*)(g_scratch + (size_t)row * F_IN);
    char4* q4 = (char4*)(q + (size_t)row * F_IN);
    int ssum = 0;
    #pragma unroll
    for (int i = 0; i < (F_IN / 4) / 256; i++) {
        const float4 v = s4[tid + i * 256];
        const int q0 = (int)fminf(fmaxf(rintf((v.x - lo) / scale) - 128.0f, -128.0f), 127.0f);
        const int q1 = (int)fminf(fmaxf(rintf((v.y - lo) / scale) - 128.0f, -128.0f), 127.0f);
        const int q2 = (int)fminf(fmaxf(rintf((v.z - lo) / scale) - 128.0f, -128.0f), 127.0f);
        const int q3 = (int)fminf(fmaxf(rintf((v.w - lo) / scale) - 128.0f, -128.0f), 127.0f);
        ssum += q0 + q1 + q2 + q3;
        char4 c;
        c.x = (signed char)q0; c.y = (signed char)q1;
        c.z = (signed char)q2; c.w = (signed char)q3;
        q4[tid + i * 256] = c;
    }
    #pragma unroll
    for (int o = 16; o > 0; o >>= 1)
        ssum += __shfl_xor_sync(0xFFFFFFFFu, ssum, o);
    __shared__ int ss[8];
    if ((tid & 31) == 0) ss[tid >> 5] = ssum;
    __syncthreads();
    if (tid == 0) {
        #pragma unroll
        for (int i = 1; i < 8; i++) ssum += ss[i];
        rowsum[row] = ssum;
    }
}

// ---------------- int8 GEMM (exact) + affine dequant epilogue ----------------
#define BM 128
#define BN 128
#define BK 64
#define SSTR 80   // padded smem row stride (bytes): conflict-free fragment loads

__device__ __forceinline__ void cp16(void* s, const void* g) {
    unsigned sa = (unsigned)__cvta_generic_to_shared(s);
    asm volatile("cp.async.cg.shared.global [%0], [%1], 16;\n" :: "r"(sa), "l"(g));
}
__device__ __forceinline__ void cp_commit() { asm volatile("cp.async.commit_group;\n"); }
__device__ __forceinline__ void cp_wait1()  { asm volatile("cp.async.wait_group 1;\n"); }

__device__ __forceinline__ void mma_s8(int* d, const int* a, const int* b) {
    asm volatile(
        "mma.sync.aligned.m16n8k32.row.col.s32.s8.s8.s32 "
        "{%0,%1,%2,%3}, {%4,%5,%6,%7}, {%8,%9}, {%0,%1,%2,%3};\n"
        : "+r"(d[0]), "+r"(d[1]), "+r"(d[2]), "+r"(d[3])
        : "r"(a[0]), "r"(a[1]), "r"(a[2]), "r"(a[3]), "r"(b[0]), "r"(b[1]));
}

__global__ __launch_bounds__(256, 1) void gemm_kernel(
    const float* __restrict__ bias, float* __restrict__ out)
{
    __shared__ signed char sA[2][BM * SSTR];
    __shared__ signed char sB[2][BN * SSTR];
    const signed char* __restrict__ A = g_qx;   // [M][K]
    const signed char* __restrict__ B = g_qw;   // [N][K] (K-contiguous = col-major operand)
    const int K = F_IN;
    const int tid = threadIdx.x;
    const int lane = tid & 31;
    const int warp = tid >> 5;
    const int wm = warp & 1;    // 2 warps along M (64 rows each)
    const int wn = warp >> 1;   // 4 warps along N (32 cols each)
    const size_t aBase = (size_t)blockIdx.y * BM * K;
    const size_t bBase = (size_t)blockIdx.x * BN * K;

    int d[16][4];
    #pragma unroll
    for (int i = 0; i < 16; i++) { d[i][0] = d[i][1] = d[i][2] = d[i][3] = 0; }

    auto load_stage = [&](int st, int k0) {
        #pragma unroll
        for (int i = 0; i < 2; i++) {
            const int idx = tid + i * 256;      // 512 x 16B per matrix
            const int row = idx >> 2;
            const int c = (idx & 3) << 4;
            cp16(&sA[st][row * SSTR + c], A + aBase + (size_t)row * K + k0 + c);
            cp16(&sB[st][row * SSTR + c], B + bBase + (size_t)row * K + k0 + c);
        }
    };

    load_stage(0, 0);  cp_commit();
    load_stage(1, BK); cp_commit();
    cp_wait1();
    __syncthreads();

    const int NK = K / BK;   // 64
    for (int kt = 0; kt < NK; kt++) {
        const int st = kt & 1;
        #pragma unroll
        for (int ks = 0; ks < 2; ks++) {
            int a[4][4], b[4][2];
            const int cb = ks * 32 + (lane & 3) * 4;
            #pragma unroll
            for (int i = 0; i < 4; i++) {
                const int r0 = wm * 64 + i * 16 + (lane >> 2);
                const signed char* p = &sA[st][r0 * SSTR + cb];
                a[i][0] = *(const int*)(p);
                a[i][1] = *(const int*)(p + 8 * SSTR);
                a[i][2] = *(const int*)(p + 16);
                a[i][3] = *(const int*)(p + 8 * SSTR + 16);
            }
            #pragma unroll
            for (int j = 0; j < 4; j++) {
                const int n0 = wn * 32 + j * 8 + (lane >> 2);
                const signed char* p = &sB[st][n0 * SSTR + cb];
                b[j][0] = *(const int*)(p);
                b[j][1] = *(const int*)(p + 16);
            }
            #pragma unroll
            for (int i = 0; i < 4; i++)
                #pragma unroll
                for (int j = 0; j < 4; j++)
                    mma_s8(d[i * 4 + j], a[i], b[j]);
        }
        __syncthreads();
        if (kt + 2 < NK) load_stage(st, (kt + 2) * BK);
        cp_commit();
        cp_wait1();
        __syncthreads();
    }

    // epilogue:  out = a*D + bx*Sx[i] + bw*Sw[j] + gamma + bias[j]
    const float lox = u2f_ord(g_mm[0]), hix = u2f_ord(g_mm[1]);
    const float low = u2f_ord(g_mm[2]), hiw = u2f_ord(g_mm[3]);
    const float sx = (hix - lox) / 255.0f;
    const float sw = (hiw - low) / 255.0f;
    const float tx = 128.0f * sx + lox;
    const float tw = 128.0f * sw + low;
    const float alpha = sx * sw;
    const float betx = sx * tw;
    const float betw = sw * tx;
    const float gam = (float)F_IN * tx * tw;
    const int N = N_ROWS;

    #pragma unroll
    for (int i = 0; i < 4; i++) {
        const int r0 = blockIdx.y * BM + wm * 64 + i * 16 + (lane >> 2);
        const float fx0 = betx * (float)g_sx[r0] + gam;
        const float fx1 = betx * (float)g_sx[r0 + 8] + gam;
        #pragma unroll
        for (int j = 0; j < 4; j++) {
            const int c0 = blockIdx.x * BN + wn * 32 + j * 8 + ((lane & 3) << 1);
            const float e0 = betw * (float)g_sw[c0] + bias[c0];
            const float e1 = betw * (float)g_sw[c0 + 1] + bias[c0 + 1];
            const int* acc = d[i * 4 + j];
            out[(size_t)r0 * N + c0]           = alpha * (float)acc[0] + fx0 + e0;
            out[(size_t)r0 * N + c0 + 1]       = alpha * (float)acc[1] + fx0 + e1;
            out[(size_t)(r0 + 8) * N + c0]     = alpha * (float)acc[2] + fx1 + e0;
            out[(size_t)(r0 + 8) * N + c0 + 1] = alpha * (float)acc[3] + fx1 + e1;
        }
    }
}

// ---------------- launch: kernel launches ONLY (graph-capturable) ----------------
extern "C" void kernel_launch(void* const* d_in, const int* in_sizes, int n_in,
                              void* d_out, int out_size)
{
    const float* x    = (const float*)d_in[0];
    const float* w    = (const float*)d_in[1];
    const float* bias = (const float*)d_in[2];
    const float* mats = (const float*)d_in[3];
    const int*   perm = (const int*)d_in[4];
    float* out = (float*)d_out;

    init_kernel<<<1, 1>>>();

    const int rotSmem = 2 * ROT_R * F_IN * (int)sizeof(float);   // 128 KB
    static bool attr_set = false;
    if (!attr_set) {
        cudaFuncSetAttribute(rotate_kernel, cudaFuncAttributeMaxDynamicSharedMemorySize, rotSmem);
        attr_set = true;
    }

    rotate_kernel<<<M_ROWS / ROT_R, ROT_T, rotSmem>>>(x, perm, mats, 0);
    quant_kernel<<<M_ROWS, 256>>>(0);
    rotate_kernel<<<N_ROWS / ROT_R, ROT_T, rotSmem>>>(w, perm, mats, 2);
    quant_kernel<<<N_ROWS, 256>>>(1);

    dim3 grid(N_ROWS / BN, M_ROWS / BM);
    gemm_kernel<<<grid, 256>>>(bias, out);
}

// round 4
// speedup vs baseline: 1.0200x; 1.0200x over previous
#include <cuda_runtime.h>
#include <cuda_bf16.h>
#include <math.h>

#define F_IN    4096
#define NBLK    2048
#define NROUNDS 12
#define M_ROWS  8192
#define N_ROWS  4096

#define ROT_R 4
#define ROT_T 512

// ---------------- scratch (static device arrays; no allocation) ----------------
__device__ float       g_scratch[(size_t)M_ROWS * F_IN];   // 128 MB, reused for x then w
__device__ signed char g_qx[(size_t)M_ROWS * F_IN];        // 32 MB
__device__ signed char g_qw[(size_t)N_ROWS * F_IN];        // 16 MB
__device__ int         g_sx[M_ROWS];
__device__ int         g_sw[N_ROWS];
__device__ unsigned    g_mm[4];                            // minx,maxx,minw,maxw (ordered-uint)

__device__ __forceinline__ unsigned f2u_ord(float f) {
    unsigned u = __float_as_uint(f);
    return (u & 0x80000000u) ? ~u : (u | 0x80000000u);
}
__device__ __forceinline__ float u2f_ord(unsigned u) {
    return __uint_as_float((u & 0x80000000u) ? (u ^ 0x80000000u) : ~u);
}

__global__ void init_kernel() {
    g_mm[0] = 0xFFFFFFFFu; g_mm[1] = 0u;
    g_mm[2] = 0xFFFFFFFFu; g_mm[3] = 0u;
}

// ---------------- rotation: 12 rounds in smem, feature-interleaved float4 ----------------
// Layout after round 0: buf4[f] = {row0,row1,row2,row3} for feature f.
// Gather of feature p = one LDS.128 (vs 4 scalar LDS in the row-major layout).
__global__ __launch_bounds__(ROT_T) void rotate_kernel(
    const float* __restrict__ src,
    const int* __restrict__ perm, const float* __restrict__ mats, int sel)
{
    extern __shared__ float sm[];
    float* bufA = sm;                    // row-major input tile / interleaved ping
    float* bufB = sm + ROT_R * F_IN;     // interleaved pong
    const int tid = threadIdx.x;
    const size_t base = (size_t)blockIdx.x * ROT_R * F_IN;

    // coalesced load of 4 rows (row-major)
    {
        const float4* g = (const float4*)(src + base);
        float4* b = (float4*)bufA;
        #pragma unroll
        for (int i = 0; i < (ROT_R * F_IN / 4) / ROT_T; i++)
            b[tid + i * ROT_T] = g[tid + i * ROT_T];
    }
    __syncthreads();

    // round 0: gather row-major -> write interleaved
    {
        const int2*   pr = (const int2*)(perm);
        const float4* mr = (const float4*)(mats);
        float4* nxt4 = (float4*)bufB;
        #pragma unroll
        for (int b = 0; b < NBLK / ROT_T; b++) {
            const int k = tid + b * ROT_T;
            const int2   p = pr[k];
            const float4 m = mr[k];
            float4 o0, o1;
            {
                float v0, v1;
                v0 = bufA[0 * F_IN + p.x]; v1 = bufA[0 * F_IN + p.y];
                o0.x = m.x * v0 + m.y * v1; o1.x = m.z * v0 + m.w * v1;
                v0 = bufA[1 * F_IN + p.x]; v1 = bufA[1 * F_IN + p.y];
                o0.y = m.x * v0 + m.y * v1; o1.y = m.z * v0 + m.w * v1;
                v0 = bufA[2 * F_IN + p.x]; v1 = bufA[2 * F_IN + p.y];
                o0.z = m.x * v0 + m.y * v1; o1.z = m.z * v0 + m.w * v1;
                v0 = bufA[3 * F_IN + p.x]; v1 = bufA[3 * F_IN + p.y];
                o0.w = m.x * v0 + m.y * v1; o1.w = m.z * v0 + m.w * v1;
            }
            nxt4[2 * k]     = o0;
            nxt4[2 * k + 1] = o1;
        }
    }
    __syncthreads();

    float* cur = bufB;
    float* nxt = bufA;
    float mn = 3.0e38f, mx = -3.0e38f;

    for (int r = 1; r < NROUNDS; r++) {
        const int2*   pr = (const int2*)(perm + r * F_IN);
        const float4* mr = (const float4*)(mats + (size_t)r * NBLK * 4);
        const float4* cur4 = (const float4*)cur;
        float4* nxt4 = (float4*)nxt;
        const bool last = (r == NROUNDS - 1);
        #pragma unroll
        for (int b = 0; b < NBLK / ROT_T; b++) {
            const int k = tid + b * ROT_T;
            const int2   p = pr[k];
            const float4 m = mr[k];
            const float4 v0 = cur4[p.x];     // LDS.128: 4 rows of feature p.x
            const float4 v1 = cur4[p.y];
            float4 o0, o1;
            o0.x = m.x * v0.x + m.y * v1.x;  o1.x = m.z * v0.x + m.w * v1.x;
            o0.y = m.x * v0.y + m.y * v1.y;  o1.y = m.z * v0.y + m.w * v1.y;
            o0.z = m.x * v0.z + m.y * v1.z;  o1.z = m.z * v0.z + m.w * v1.z;
            o0.w = m.x * v0.w + m.y * v1.w;  o1.w = m.z * v0.w + m.w * v1.w;
            nxt4[2 * k]     = o0;
            nxt4[2 * k + 1] = o1;
            if (last) {
                mn = fminf(mn, fminf(fminf(o0.x, o0.y), fminf(o0.z, o0.w)));
                mn = fminf(mn, fminf(fminf(o1.x, o1.y), fminf(o1.z, o1.w)));
                mx = fmaxf(mx, fmaxf(fmaxf(o0.x, o0.y), fmaxf(o0.z, o0.w)));
                mx = fmaxf(mx, fmaxf(fmaxf(o1.x, o1.y), fmaxf(o1.z, o1.w)));
            }
        }
        __syncthreads();
        float* t = cur; cur = nxt; nxt = t;
    }

    // un-interleave in registers, write row-major scratch (coalesced per row)
    {
        const float4* cur4 = (const float4*)cur;
        float* dst = g_scratch + base;
        #pragma unroll
        for (int i = 0; i < F_IN / ROT_T; i++) {
            const int f = tid + i * ROT_T;
            const float4 v = cur4[f];
            dst[0 * F_IN + f] = v.x;
            dst[1 * F_IN + f] = v.y;
            dst[2 * F_IN + f] = v.z;
            dst[3 * F_IN + f] = v.w;
        }
    }

    // block-reduce min/max -> one atomic pair per CTA
    #pragma unroll
    for (int o = 16; o > 0; o >>= 1) {
        mn = fminf(mn, __shfl_xor_sync(0xFFFFFFFFu, mn, o));
        mx = fmaxf(mx, __shfl_xor_sync(0xFFFFFFFFu, mx, o));
    }
    __shared__ float smn[ROT_T / 32], smx[ROT_T / 32];
    const int w = tid >> 5;
    if ((tid & 31) == 0) { smn[w] = mn; smx[w] = mx; }
    __syncthreads();
    if (tid == 0) {
        #pragma unroll
        for (int i = 1; i < ROT_T / 32; i++) {
            mn = fminf(mn, smn[i]); mx = fmaxf(mx, smx[i]);
        }
        atomicMin(&g_mm[sel], f2u_ord(mn));
        atomicMax(&g_mm[sel + 1], f2u_ord(mx));
    }
}

// ---------------- quantize: q = clip(round((t-lo)/s) - 128), + per-row sums ----------------
__global__ __launch_bounds__(256) void quant_kernel(int sel)
{
    const int row = blockIdx.x;
    const int tid = threadIdx.x;
    signed char* q = sel ? g_qw : g_qx;
    int* rowsum    = sel ? g_sw : g_sx;
    const float lo = u2f_ord(g_mm[sel ? 2 : 0]);
    const float hi = u2f_ord(g_mm[sel ? 3 : 1]);
    const float scale = (hi - lo) / 255.0f;

    const float4* s4 = (const float4*)(g_scratch + (size_t)row * F_IN);
    char4* q4 = (char4*)(q + (size_t)row * F_IN);
    int ssum = 0;
    #pragma unroll
    for (int i = 0; i < (F_IN / 4) / 256; i++) {
        const float4 v = s4[tid + i * 256];
        const int q0 = (int)fminf(fmaxf(rintf((v.x - lo) / scale) - 128.0f, -128.0f), 127.0f);
        const int q1 = (int)fminf(fmaxf(rintf((v.y - lo) / scale) - 128.0f, -128.0f), 127.0f);
        const int q2 = (int)fminf(fmaxf(rintf((v.z - lo) / scale) - 128.0f, -128.0f), 127.0f);
        const int q3 = (int)fminf(fmaxf(rintf((v.w - lo) / scale) - 128.0f, -128.0f), 127.0f);
        ssum += q0 + q1 + q2 + q3;
        char4 c;
        c.x = (signed char)q0; c.y = (signed char)q1;
        c.z = (signed char)q2; c.w = (signed char)q3;
        q4[tid + i * 256] = c;
    }
    #pragma unroll
    for (int o = 16; o > 0; o >>= 1)
        ssum += __shfl_xor_sync(0xFFFFFFFFu, ssum, o);
    __shared__ int ss[8];
    if ((tid & 31) == 0) ss[tid >> 5] = ssum;
    __syncthreads();
    if (tid == 0) {
        #pragma unroll
        for (int i = 1; i < 8; i++) ssum += ss[i];
        rowsum[row] = ssum;
    }
}

// ---------------- int8 GEMM: BK=128, 3-stage cp.async, ldmatrix fragments ----------------
#define BM 128
#define BN 128
#define BK 128
#define GSTAGES 3
#define SSTR 144   // 128B data + 16B pad: ldmatrix rows land on distinct 4-bank groups

#define A_STAGE_BYTES (BM * SSTR)
#define B_STAGE_BYTES (BN * SSTR)
#define GEMM_SMEM (GSTAGES * (A_STAGE_BYTES + B_STAGE_BYTES))

__device__ __forceinline__ void cp16(void* s, const void* g) {
    unsigned sa = (unsigned)__cvta_generic_to_shared(s);
    asm volatile("cp.async.cg.shared.global [%0], [%1], 16;\n" :: "r"(sa), "l"(g));
}
__device__ __forceinline__ void cp_commit() { asm volatile("cp.async.commit_group;\n"); }
__device__ __forceinline__ void cp_wait1()  { asm volatile("cp.async.wait_group 1;\n"); }
__device__ __forceinline__ void cp_wait0()  { asm volatile("cp.async.wait_group 0;\n"); }

__device__ __forceinline__ void ldsm4(int* r, const void* p) {
    unsigned a = (unsigned)__cvta_generic_to_shared(p);
    asm volatile("ldmatrix.sync.aligned.m8n8.x4.shared.b16 {%0,%1,%2,%3}, [%4];\n"
                 : "=r"(r[0]), "=r"(r[1]), "=r"(r[2]), "=r"(r[3]) : "r"(a));
}
__device__ __forceinline__ void ldsm2(int* r, const void* p) {
    unsigned a = (unsigned)__cvta_generic_to_shared(p);
    asm volatile("ldmatrix.sync.aligned.m8n8.x2.shared.b16 {%0,%1}, [%2];\n"
                 : "=r"(r[0]), "=r"(r[1]) : "r"(a));
}

__device__ __forceinline__ void mma_s8(int* d, const int* a, const int* b) {
    asm volatile(
        "mma.sync.aligned.m16n8k32.row.col.s32.s8.s8.s32 "
        "{%0,%1,%2,%3}, {%4,%5,%6,%7}, {%8,%9}, {%0,%1,%2,%3};\n"
        : "+r"(d[0]), "+r"(d[1]), "+r"(d[2]), "+r"(d[3])
        : "r"(a[0]), "r"(a[1]), "r"(a[2]), "r"(a[3]), "r"(b[0]), "r"(b[1]));
}

__global__ __launch_bounds__(256, 1) void gemm_kernel(
    const float* __restrict__ bias, float* __restrict__ out)
{
    extern __shared__ signed char gsm[];
    const signed char* __restrict__ A = g_qx;   // [M][K]
    const signed char* __restrict__ B = g_qw;   // [N][K]
    const int K = F_IN;
    const int tid = threadIdx.x;
    const int lane = tid & 31;
    const int warp = tid >> 5;
    const int wm = warp & 1;    // 2 warps along M (64 rows each)
    const int wn = warp >> 1;   // 4 warps along N (32 cols each)
    const size_t aBase = (size_t)blockIdx.y * BM * K;
    const size_t bBase = (size_t)blockIdx.x * BN * K;

    int d[16][4];
    #pragma unroll
    for (int i = 0; i < 16; i++) { d[i][0] = d[i][1] = d[i][2] = d[i][3] = 0; }

    auto load_stage = [&](int st, int k0) {
        signed char* sa = gsm + st * A_STAGE_BYTES;
        signed char* sb = gsm + GSTAGES * A_STAGE_BYTES + st * B_STAGE_BYTES;
        #pragma unroll
        for (int i = 0; i < 4; i++) {
            const int idx = tid + i * 256;          // 1024 x 16B per matrix
            const int row = idx >> 3;
            const int c = (idx & 7) << 4;
            cp16(sa + row * SSTR + c, A + aBase + (size_t)row * K + k0 + c);
            cp16(sb + row * SSTR + c, B + bBase + (size_t)row * K + k0 + c);
        }
        cp_commit();
    };

    load_stage(0, 0);
    load_stage(1, BK);

    // precomputed lane address components for ldmatrix
    const int a_row_off = ((lane >> 3) & 1) * 8 + (lane & 7);
    const int a_col_off = (lane >> 4) * 16;
    const int b_row_off = (lane & 7);
    const int b_col_off = ((lane >> 3) & 1) * 16;

    const int NK = K / BK;   // 32
    for (int kt = 0; kt < NK; kt++) {
        const int st = kt % GSTAGES;
        if (kt + 2 < NK) cp_wait1(); else cp_wait0();
        __syncthreads();

        const signed char* sa = gsm + st * A_STAGE_BYTES;
        const signed char* sb = gsm + GSTAGES * A_STAGE_BYTES + st * B_STAGE_BYTES;
        #pragma unroll
        for (int ks = 0; ks < 4; ks++) {
            const int cb = ks * 32;
            int a[4][4], b[4][2];
            #pragma unroll
            for (int i = 0; i < 4; i++) {
                const int r0 = wm * 64 + i * 16 + a_row_off;
                ldsm4(a[i], sa + r0 * SSTR + cb + a_col_off);
            }
            #pragma unroll
            for (int j = 0; j < 4; j++) {
                const int n0 = wn * 32 + j * 8 + b_row_off;
                ldsm2(b[j], sb + n0 * SSTR + cb + b_col_off);
            }
            #pragma unroll
            for (int i = 0; i < 4; i++)
                #pragma unroll
                for (int j = 0; j < 4; j++)
                    mma_s8(d[i * 4 + j], a[i], b[j]);
        }

        if (kt + 2 < NK) load_stage((kt + 2) % GSTAGES, (kt + 2) * BK);
    }

    // epilogue:  out = alpha*D + betx*Sx[i] + betw*Sw[j] + gam + bias[j]
    const float lox = u2f_ord(g_mm[0]), hix = u2f_ord(g_mm[1]);
    const float low = u2f_ord(g_mm[2]), hiw = u2f_ord(g_mm[3]);
    const float sx = (hix - lox) / 255.0f;
    const float sw = (hiw - low) / 255.0f;
    const float tx = 128.0f * sx + lox;
    const float tw = 128.0f * sw + low;
    const float alpha = sx * sw;
    const float betx = sx * tw;
    const float betw = sw * tx;
    const float gam = (float)F_IN * tx * tw;
    const int N = N_ROWS;

    #pragma unroll
    for (int i = 0; i < 4; i++) {
        const int r0 = blockIdx.y * BM + wm * 64 + i * 16 + (lane >> 2);
        const float fx0 = betx * (float)g_sx[r0] + gam;
        const float fx1 = betx * (float)g_sx[r0 + 8] + gam;
        #pragma unroll
        for (int j = 0; j < 4; j++) {
            const int c0 = blockIdx.x * BN + wn * 32 + j * 8 + ((lane & 3) << 1);
            const float e0 = betw * (float)g_sw[c0] + bias[c0];
            const float e1 = betw * (float)g_sw[c0 + 1] + bias[c0 + 1];
            const int* acc = d[i * 4 + j];
            float2 lo2, hi2;
            lo2.x = alpha * (float)acc[0] + fx0 + e0;
            lo2.y = alpha * (float)acc[1] + fx0 + e1;
            hi2.x = alpha * (float)acc[2] + fx1 + e0;
            hi2.y = alpha * (float)acc[3] + fx1 + e1;
            *(float2*)(out + (size_t)r0 * N + c0)       = lo2;
            *(float2*)(out + (size_t)(r0 + 8) * N + c0) = hi2;
        }
    }
}

// ---------------- launch: kernel launches ONLY (graph-capturable) ----------------
extern "C" void kernel_launch(void* const* d_in, const int* in_sizes, int n_in,
                              void* d_out, int out_size)
{
    const float* x    = (const float*)d_in[0];
    const float* w    = (const float*)d_in[1];
    const float* bias = (const float*)d_in[2];
    const float* mats = (const float*)d_in[3];
    const int*   perm = (const int*)d_in[4];
    float* out = (float*)d_out;

    const int rotSmem = 2 * ROT_R * F_IN * (int)sizeof(float);   // 128 KB
    static bool attr_set = false;
    if (!attr_set) {
        cudaFuncSetAttribute(rotate_kernel, cudaFuncAttributeMaxDynamicSharedMemorySize, rotSmem);
        cudaFuncSetAttribute(gemm_kernel, cudaFuncAttributeMaxDynamicSharedMemorySize, GEMM_SMEM);
        attr_set = true;
    }

    init_kernel<<<1, 1>>>();

    rotate_kernel<<<M_ROWS / ROT_R, ROT_T, rotSmem>>>(x, perm, mats, 0);
    quant_kernel<<<M_ROWS, 256>>>(0);
    rotate_kernel<<<N_ROWS / ROT_R, ROT_T, rotSmem>>>(w, perm, mats, 2);
    quant_kernel<<<N_ROWS, 256>>>(1);

    dim3 grid(N_ROWS / BN, M_ROWS / BM);
    gemm_kernel<<<grid, 256, GEMM_SMEM>>>(bias, out);
}

// round 11
// speedup vs baseline: 1.0614x; 1.0405x over previous
#include <cuda_runtime.h>
#include <cuda_bf16.h>
#include <cstdint>
#include <math.h>

#define F_IN    4096
#define NBLK    2048
#define NROUNDS 12
#define NDR     6          // 6 fused double-rounds
#define M_ROWS  8192
#define N_ROWS  4096

#define ROT_R 4
#define ROT_T 512

// ---------------- scratch (static device arrays; no allocation) ----------------
__device__ float       g_scratch[(size_t)M_ROWS * F_IN];   // 128 MB, reused x then w
__device__ signed char g_qx[(size_t)M_ROWS * F_IN];        // 32 MB
__device__ signed char g_qw[(size_t)N_ROWS * F_IN];        // 16 MB
__device__ int         g_sx[M_ROWS];
__device__ int         g_sw[N_ROWS];
__device__ unsigned    g_mm[4];                            // minx,maxx,minw,maxw (ordered-uint)

// fused double-round tables (prep_kernel output; L2-resident, reused by all CTAs)
__device__ int4   g_fidx[NDR * NBLK];   // 4 source features per dest pair
__device__ float4 g_fw0[NDR * NBLK];    // coeff row for dest element 0
__device__ float4 g_fw1[NDR * NBLK];    // coeff row for dest element 1

__device__ __forceinline__ unsigned f2u_ord(float f) {
    unsigned u = __float_as_uint(f);
    return (u & 0x80000000u) ? ~u : (u | 0x80000000u);
}
__device__ __forceinline__ float u2f_ord(unsigned u) {
    return __uint_as_float((u & 0x80000000u) ? (u ^ 0x80000000u) : ~u);
}

__global__ void init_kernel() {
    g_mm[0] = 0xFFFFFFFFu; g_mm[1] = 0u;
    g_mm[2] = 0xFFFFFFFFu; g_mm[3] = 0u;
}

// ---------------- prep: fuse round pairs (2dr, 2dr+1) into gather4 + 2x4 coeffs ----------------
// round r: v1[2m+b] = sum_c M_r[m][b][c] * v0[p_r[2m+c]]
// fused:   v2[2k+a] = sum_{b,c} M_{r1}[k][a][b] * M_{r0}[m_b][bit_b][c] * v0[p_{r0}[2*m_b+c]]
__global__ __launch_bounds__(256) void prep_kernel(
    const int* __restrict__ perm, const float* __restrict__ mats)
{
    const int idx = blockIdx.x * 256 + threadIdx.x;
    if (idx >= NDR * NBLK) return;
    const int dr = idx / NBLK;
    const int k  = idx % NBLK;
    const int r0 = 2 * dr, r1 = 2 * dr + 1;

    const int j0 = perm[r1 * F_IN + 2 * k];
    const int j1 = perm[r1 * F_IN + 2 * k + 1];
    const int m0 = j0 >> 1, b0 = j0 & 1;
    const int m1 = j1 >> 1, b1 = j1 & 1;

    int4 s;
    s.x = perm[r0 * F_IN + 2 * m0];
    s.y = perm[r0 * F_IN + 2 * m0 + 1];
    s.z = perm[r0 * F_IN + 2 * m1];
    s.w = perm[r0 * F_IN + 2 * m1 + 1];

    const float4* m4 = (const float4*)mats;            // row-major 2x2: {00,01,10,11}
    const float4 M1 = m4[(size_t)r1 * NBLK + k];
    const float4 Ma = m4[(size_t)r0 * NBLK + m0];
    const float4 Mb = m4[(size_t)r0 * NBLK + m1];
    const float a0 = b0 ? Ma.z : Ma.x, a1 = b0 ? Ma.w : Ma.y;   // row bit_b of M_{r0}[m_b]
    const float c0 = b1 ? Mb.z : Mb.x, c1 = b1 ? Mb.w : Mb.y;

    g_fidx[idx] = s;
    g_fw0[idx] = make_float4(M1.x * a0, M1.x * a1, M1.y * c0, M1.y * c1);
    g_fw1[idx] = make_float4(M1.z * a0, M1.z * a1, M1.w * c0, M1.w * c1);
}

// ---------------- rotation: 6 fused stages in smem, feature-interleaved float4 ----------------
__global__ __launch_bounds__(ROT_T) void rotate_kernel(
    const float* __restrict__ src, int sel)
{
    extern __shared__ float sm[];
    float* bufA = sm;
    float* bufB = sm + ROT_R * F_IN;
    const int tid = threadIdx.x;
    const size_t base = (size_t)blockIdx.x * ROT_R * F_IN;

    // coalesced load of 4 rows (row-major into bufA)
    {
        const float4* g = (const float4*)(src + base);
        float4* b = (float4*)bufA;
        #pragma unroll
        for (int i = 0; i < (ROT_R * F_IN / 4) / ROT_T; i++)
            b[tid + i * ROT_T] = g[tid + i * ROT_T];
    }
    __syncthreads();

    // interleave: bufB4[f] = {row0[f], row1[f], row2[f], row3[f]}  (conflict-free reads)
    {
        float4* b4 = (float4*)bufB;
        #pragma unroll
        for (int i = 0; i < F_IN / ROT_T; i++) {
            const int f = tid + i * ROT_T;
            float4 v;
            v.x = bufA[0 * F_IN + f];
            v.y = bufA[1 * F_IN + f];
            v.z = bufA[2 * F_IN + f];
            v.w = bufA[3 * F_IN + f];
            b4[f] = v;
        }
    }
    __syncthreads();

    float* cur = bufB;
    float* nxt = bufA;
    float mn = 3.0e38f, mx = -3.0e38f;

    for (int dr = 0; dr < NDR; dr++) {
        const int4*   fi  = g_fidx + dr * NBLK;
        const float4* w0p = g_fw0 + dr * NBLK;
        const float4* w1p = g_fw1 + dr * NBLK;
        const float4* cur4 = (const float4*)cur;
        float4* nxt4 = (float4*)nxt;
        const bool last = (dr == NDR - 1);
        #pragma unroll
        for (int b = 0; b < NBLK / ROT_T; b++) {
            const int k = tid + b * ROT_T;
            const int4   s  = fi[k];
            const float4 w0 = w0p[k];
            const float4 w1 = w1p[k];
            const float4 va = cur4[s.x];   // LDS.128 gathers
            const float4 vb = cur4[s.y];
            const float4 vc = cur4[s.z];
            const float4 vd = cur4[s.w];
            float4 o0, o1;
            o0.x = w0.x * va.x + w0.y * vb.x + w0.z * vc.x + w0.w * vd.x;
            o0.y = w0.x * va.y + w0.y * vb.y + w0.z * vc.y + w0.w * vd.y;
            o0.z = w0.x * va.z + w0.y * vb.z + w0.z * vc.z + w0.w * vd.z;
            o0.w = w0.x * va.w + w0.y * vb.w + w0.z * vc.w + w0.w * vd.w;
            o1.x = w1.x * va.x + w1.y * vb.x + w1.z * vc.x + w1.w * vd.x;
            o1.y = w1.x * va.y + w1.y * vb.y + w1.z * vc.y + w1.w * vd.y;
            o1.z = w1.x * va.z + w1.y * vb.z + w1.z * vc.z + w1.w * vd.z;
            o1.w = w1.x * va.w + w1.y * vb.w + w1.z * vc.w + w1.w * vd.w;
            nxt4[2 * k]     = o0;
            nxt4[2 * k + 1] = o1;
            if (last) {
                mn = fminf(mn, fminf(fminf(o0.x, o0.y), fminf(o0.z, o0.w)));
                mn = fminf(mn, fminf(fminf(o1.x, o1.y), fminf(o1.z, o1.w)));
                mx = fmaxf(mx, fmaxf(fmaxf(o0.x, o0.y), fmaxf(o0.z, o0.w)));
                mx = fmaxf(mx, fmaxf(fmaxf(o1.x, o1.y), fmaxf(o1.z, o1.w)));
            }
        }
        __syncthreads();
        float* t = cur; cur = nxt; nxt = t;
    }

    // un-interleave in registers, write row-major scratch (coalesced per row)
    {
        const float4* cur4 = (const float4*)cur;
        float* dst = g_scratch + base;
        #pragma unroll
        for (int i = 0; i < F_IN / ROT_T; i++) {
            const int f = tid + i * ROT_T;
            const float4 v = cur4[f];
            dst[0 * F_IN + f] = v.x;
            dst[1 * F_IN + f] = v.y;
            dst[2 * F_IN + f] = v.z;
            dst[3 * F_IN + f] = v.w;
        }
    }

    // block-reduce min/max -> one atomic pair per CTA
    #pragma unroll
    for (int o = 16; o > 0; o >>= 1) {
        mn = fminf(mn, __shfl_xor_sync(0xFFFFFFFFu, mn, o));
        mx = fmaxf(mx, __shfl_xor_sync(0xFFFFFFFFu, mx, o));
    }
    __shared__ float smn[ROT_T / 32], smx[ROT_T / 32];
    const int w = tid >> 5;
    if ((tid & 31) == 0) { smn[w] = mn; smx[w] = mx; }
    __syncthreads();
    if (tid == 0) {
        #pragma unroll
        for (int i = 1; i < ROT_T / 32; i++) {
            mn = fminf(mn, smn[i]); mx = fmaxf(mx, smx[i]);
        }
        atomicMin(&g_mm[sel], f2u_ord(mn));
        atomicMax(&g_mm[sel + 1], f2u_ord(mx));
    }
}

// ---------------- quantize: q = clip(round((t-lo)/s) - 128), + per-row sums ----------------
__global__ __launch_bounds__(256) void quant_kernel(int sel)
{
    const int row = blockIdx.x;
    const int tid = threadIdx.x;
    signed char* q = sel ? g_qw : g_qx;
    int* rowsum    = sel ? g_sw : g_sx;
    const float lo = u2f_ord(g_mm[sel ? 2 : 0]);
    const float hi = u2f_ord(g_mm[sel ? 3 : 1]);
    const float scale = (hi - lo) / 255.0f;

    const float4* s4 = (const float4*)(g_scratch + (size_t)row * F_IN);
    char4* q4 = (char4*)(q + (size_t)row * F_IN);
    int ssum = 0;
    #pragma unroll
    for (int i = 0; i < (F_IN / 4) / 256; i++) {
        const float4 v = s4[tid + i * 256];
        const int q0 = (int)fminf(fmaxf(rintf((v.x - lo) / scale) - 128.0f, -128.0f), 127.0f);
        const int q1 = (int)fminf(fmaxf(rintf((v.y - lo) / scale) - 128.0f, -128.0f), 127.0f);
        const int q2 = (int)fminf(fmaxf(rintf((v.z - lo) / scale) - 128.0f, -128.0f), 127.0f);
        const int q3 = (int)fminf(fmaxf(rintf((v.w - lo) / scale) - 128.0f, -128.0f), 127.0f);
        ssum += q0 + q1 + q2 + q3;
        char4 c;
        c.x = (signed char)q0; c.y = (signed char)q1;
        c.z = (signed char)q2; c.w = (signed char)q3;
        q4[tid + i * 256] = c;
    }
    #pragma unroll
    for (int o = 16; o > 0; o >>= 1)
        ssum += __shfl_xor_sync(0xFFFFFFFFu, ssum, o);
    __shared__ int ss[8];
    if ((tid & 31) == 0) ss[tid >> 5] = ssum;
    __syncthreads();
    if (tid == 0) {
        #pragma unroll
        for (int i = 1; i < 8; i++) ssum += ss[i];
        rowsum[row] = ssum;
    }
}

// ---------------- int8 GEMM (R4 verbatim — at the fallback-IMMA floor) ----------------
#define BM 128
#define BN 128
#define BK 128
#define GSTAGES 3
#define SSTR 144   // 128B data + 16B pad: ldmatrix rows land on distinct 4-bank groups

#define A_STAGE_BYTES (BM * SSTR)
#define B_STAGE_BYTES (BN * SSTR)
#define GEMM_SMEM (GSTAGES * (A_STAGE_BYTES + B_STAGE_BYTES))

__device__ __forceinline__ void cp16(void* s, const void* g) {
    unsigned sa = (unsigned)__cvta_generic_to_shared(s);
    asm volatile("cp.async.cg.shared.global [%0], [%1], 16;\n" :: "r"(sa), "l"(g));
}
__device__ __forceinline__ void cp_commit() { asm volatile("cp.async.commit_group;\n"); }
__device__ __forceinline__ void cp_wait1()  { asm volatile("cp.async.wait_group 1;\n"); }
__device__ __forceinline__ void cp_wait0()  { asm volatile("cp.async.wait_group 0;\n"); }

__device__ __forceinline__ void ldsm4(int* r, const void* p) {
    unsigned a = (unsigned)__cvta_generic_to_shared(p);
    asm volatile("ldmatrix.sync.aligned.m8n8.x4.shared.b16 {%0,%1,%2,%3}, [%4];\n"
                 : "=r"(r[0]), "=r"(r[1]), "=r"(r[2]), "=r"(r[3]) : "r"(a));
}
__device__ __forceinline__ void ldsm2(int* r, const void* p) {
    unsigned a = (unsigned)__cvta_generic_to_shared(p);
    asm volatile("ldmatrix.sync.aligned.m8n8.x2.shared.b16 {%0,%1}, [%2];\n"
                 : "=r"(r[0]), "=r"(r[1]) : "r"(a));
}

__device__ __forceinline__ void mma_s8(int* d, const int* a, const int* b) {
    asm volatile(
        "mma.sync.aligned.m16n8k32.row.col.s32.s8.s8.s32 "
        "{%0,%1,%2,%3}, {%4,%5,%6,%7}, {%8,%9}, {%0,%1,%2,%3};\n"
        : "+r"(d[0]), "+r"(d[1]), "+r"(d[2]), "+r"(d[3])
        : "r"(a[0]), "r"(a[1]), "r"(a[2]), "r"(a[3]), "r"(b[0]), "r"(b[1]));
}

__global__ __launch_bounds__(256, 1) void gemm_kernel(
    const float* __restrict__ bias, float* __restrict__ out)
{
    extern __shared__ signed char gsm[];
    const signed char* __restrict__ A = g_qx;   // [M][K]
    const signed char* __restrict__ B = g_qw;   // [N][K]
    const int K = F_IN;
    const int tid = threadIdx.x;
    const int lane = tid & 31;
    const int warp = tid >> 5;
    const int wm = warp & 1;    // 2 warps along M (64 rows each)
    const int wn = warp >> 1;   // 4 warps along N (32 cols each)
    const size_t aBase = (size_t)blockIdx.y * BM * K;
    const size_t bBase = (size_t)blockIdx.x * BN * K;

    int d[16][4];
    #pragma unroll
    for (int i = 0; i < 16; i++) { d[i][0] = d[i][1] = d[i][2] = d[i][3] = 0; }

    auto load_stage = [&](int st, int k0) {
        signed char* sa = gsm + st * A_STAGE_BYTES;
        signed char* sb = gsm + GSTAGES * A_STAGE_BYTES + st * B_STAGE_BYTES;
        #pragma unroll
        for (int i = 0; i < 4; i++) {
            const int idx = tid + i * 256;          // 1024 x 16B per matrix
            const int row = idx >> 3;
            const int c = (idx & 7) << 4;
            cp16(sa + row * SSTR + c, A + aBase + (size_t)row * K + k0 + c);
            cp16(sb + row * SSTR + c, B + bBase + (size_t)row * K + k0 + c);
        }
        cp_commit();
    };

    load_stage(0, 0);
    load_stage(1, BK);

    const int a_row_off = ((lane >> 3) & 1) * 8 + (lane & 7);
    const int a_col_off = (lane >> 4) * 16;
    const int b_row_off = (lane & 7);
    const int b_col_off = ((lane >> 3) & 1) * 16;

    const int NK = K / BK;   // 32
    for (int kt = 0; kt < NK; kt++) {
        const int st = kt % GSTAGES;
        if (kt + 2 < NK) cp_wait1(); else cp_wait0();
        __syncthreads();

        const signed char* sa = gsm + st * A_STAGE_BYTES;
        const signed char* sb = gsm + GSTAGES * A_STAGE_BYTES + st * B_STAGE_BYTES;
        #pragma unroll
        for (int ks = 0; ks < 4; ks++) {
            const int cb = ks * 32;
            int a[4][4], b[4][2];
            #pragma unroll
            for (int i = 0; i < 4; i++) {
                const int r0 = wm * 64 + i * 16 + a_row_off;
                ldsm4(a[i], sa + r0 * SSTR + cb + a_col_off);
            }
            #pragma unroll
            for (int j = 0; j < 4; j++) {
                const int n0 = wn * 32 + j * 8 + b_row_off;
                ldsm2(b[j], sb + n0 * SSTR + cb + b_col_off);
            }
            #pragma unroll
            for (int i = 0; i < 4; i++)
                #pragma unroll
                for (int j = 0; j < 4; j++)
                    mma_s8(d[i * 4 + j], a[i], b[j]);
        }

        if (kt + 2 < NK) load_stage((kt + 2) % GSTAGES, (kt + 2) * BK);
    }

    // epilogue:  out = alpha*D + betx*Sx[i] + betw*Sw[j] + gam + bias[j]
    const float lox = u2f_ord(g_mm[0]), hix = u2f_ord(g_mm[1]);
    const float low = u2f_ord(g_mm[2]), hiw = u2f_ord(g_mm[3]);
    const float sx = (hix - lox) / 255.0f;
    const float sw = (hiw - low) / 255.0f;
    const float tx = 128.0f * sx + lox;
    const float tw = 128.0f * sw + low;
    const float alpha = sx * sw;
    const float betx = sx * tw;
    const float betw = sw * tx;
    const float gam = (float)F_IN * tx * tw;
    const int N = N_ROWS;

    #pragma unroll
    for (int i = 0; i < 4; i++) {
        const int r0 = blockIdx.y * BM + wm * 64 + i * 16 + (lane >> 2);
        const float fx0 = betx * (float)g_sx[r0] + gam;
        const float fx1 = betx * (float)g_sx[r0 + 8] + gam;
        #pragma unroll
        for (int j = 0; j < 4; j++) {
            const int c0 = blockIdx.x * BN + wn * 32 + j * 8 + ((lane & 3) << 1);
            const float e0 = betw * (float)g_sw[c0] + bias[c0];
            const float e1 = betw * (float)g_sw[c0 + 1] + bias[c0 + 1];
            const int* acc = d[i * 4 + j];
            float2 lo2, hi2;
            lo2.x = alpha * (float)acc[0] + fx0 + e0;
            lo2.y = alpha * (float)acc[1] + fx0 + e1;
            hi2.x = alpha * (float)acc[2] + fx1 + e0;
            hi2.y = alpha * (float)acc[3] + fx1 + e1;
            *(float2*)(out + (size_t)r0 * N + c0)       = lo2;
            *(float2*)(out + (size_t)(r0 + 8) * N + c0) = hi2;
        }
    }
}

// ---------------- launch: kernel launches ONLY (graph-capturable) ----------------
extern "C" void kernel_launch(void* const* d_in, const int* in_sizes, int n_in,
                              void* d_out, int out_size)
{
    const float* x    = (const float*)d_in[0];
    const float* w    = (const float*)d_in[1];
    const float* bias = (const float*)d_in[2];
    const float* mats = (const float*)d_in[3];
    const int*   perm = (const int*)d_in[4];
    float* out = (float*)d_out;

    const int rotSmem = 2 * ROT_R * F_IN * (int)sizeof(float);   // 128 KB
    static bool attr_set = false;
    if (!attr_set) {
        cudaFuncSetAttribute(rotate_kernel, cudaFuncAttributeMaxDynamicSharedMemorySize, rotSmem);
        cudaFuncSetAttribute(gemm_kernel, cudaFuncAttributeMaxDynamicSharedMemorySize, GEMM_SMEM);
        attr_set = true;
    }

    init_kernel<<<1, 1>>>();
    prep_kernel<<<(NDR * NBLK + 255) / 256, 256>>>(perm, mats);

    rotate_kernel<<<M_ROWS / ROT_R, ROT_T, rotSmem>>>(x, 0);
    quant_kernel<<<M_ROWS, 256>>>(0);
    rotate_kernel<<<N_ROWS / ROT_R, ROT_T, rotSmem>>>(w, 2);
    quant_kernel<<<N_ROWS, 256>>>(1);

    dim3 grid(N_ROWS / BN, M_ROWS / BM);
    gemm_kernel<<<grid, 256, GEMM_SMEM>>>(bias, out);
}